// round 14
// baseline (speedup 1.0000x reference)
#include <cuda_runtime.h>
#include <cuda_bf16.h>
#include <cstdint>
#include <cstddef>

#define VOCAB   100000
#define EMB     256
#define NS      256
#define BATCH   16384
#define KPAD    264              // bf16 elems per smem row (256+8 -> conflict-free ldmatrix)

#define K1_BLK  512              // gather kernel: 512 blocks x 256 thr, 32 rows each
#define K1_ROWS 32
#define K2_BLK  128              // gemm kernel: 128 blocks x 512 thr, 128 rows each
#define K2_ROWS 128

__device__ __nv_bfloat16 g_abf[BATCH * EMB];   // bf16 embed copy (8 MB, L2-resident)
__device__ __nv_bfloat16 g_wbf[NS * EMB];      // bf16 sampled weights (128 KB)
__device__ float g_corr[NS];
__device__ float g_tl[K1_BLK];                 // true-logit partials from K1
__device__ float g_partials[K2_BLK];
__device__ int   g_count = 0;

__device__ __forceinline__ uint32_t smem_u32(const void* p) {
    return (uint32_t)__cvta_generic_to_shared(p);
}

__device__ __forceinline__ void ldsm_x4(uint32_t& r0, uint32_t& r1, uint32_t& r2, uint32_t& r3,
                                        uint32_t addr) {
    asm volatile("ldmatrix.sync.aligned.m8n8.x4.shared.b16 {%0,%1,%2,%3}, [%4];"
                 : "=r"(r0), "=r"(r1), "=r"(r2), "=r"(r3) : "r"(addr));
}

__device__ __forceinline__ void mma_bf16(float& c0, float& c1, float& c2, float& c3,
                                         uint32_t a0, uint32_t a1, uint32_t a2, uint32_t a3,
                                         uint32_t b0, uint32_t b1) {
    asm volatile("mma.sync.aligned.m16n8k16.row.col.f32.bf16.bf16.f32 "
                 "{%0,%1,%2,%3}, {%4,%5,%6,%7}, {%8,%9}, {%0,%1,%2,%3};"
                 : "+f"(c0), "+f"(c1), "+f"(c2), "+f"(c3)
                 : "r"(a0), "r"(a1), "r"(a2), "r"(a3), "r"(b0), "r"(b1));
}

__device__ __forceinline__ uint2 pack_bf16x4(float4 v) {
    __nv_bfloat162 p0 = __floats2bfloat162_rn(v.x, v.y);
    __nv_bfloat162 p1 = __floats2bfloat162_rn(v.z, v.w);
    uint2 u;
    u.x = *(uint32_t*)&p0;
    u.y = *(uint32_t*)&p1;
    return u;
}

__device__ __forceinline__ void stcs128(float* p, float4 v) {
    asm volatile("st.global.cs.v4.f32 [%0], {%1,%2,%3,%4};"
                 :: "l"(p), "f"(v.x), "f"(v.y), "f"(v.z), "f"(v.w) : "memory");
}

// ======================= K1: bandwidth kernel ============================
// High occupancy (tiny smem, modest regs). All DRAM-heavy work lives here.
__global__ void __launch_bounds__(256) w2v_gather(
    const float* __restrict__ emb,
    const float* __restrict__ ncew,
    const float* __restrict__ nceb,
    const int* __restrict__ inputs,
    const int* __restrict__ labels,
    const int* __restrict__ sids,
    float* __restrict__ out)
{
    __shared__ int   sRow[K1_ROWS];
    __shared__ float sRed[8];

    const int tid = threadIdx.x;
    const int bid = blockIdx.x;
    const int R0  = bid * K1_ROWS;
    const int warp = tid >> 5;
    const int lane = tid & 31;
    const float INV_LOGV = 1.0f / logf((float)VOCAB + 1.0f);

    if (tid < K1_ROWS) sRow[tid] = inputs[R0 + tid];

    // Side jobs spread over blocks: W bf16 conversion + corr table
    if (bid < 64) {                      // 64 blocks x 4 W rows
        int r = bid * 4 + (tid >> 6), c4 = tid & 63;
        float4 v = __ldg((const float4*)(ncew + (size_t)__ldg(sids + r) * EMB + c4 * 4));
        *(uint2*)(g_wbf + (size_t)r * EMB + c4 * 4) = pack_bf16x4(v);
    } else if (bid == 64) {              // corr: 256 threads = NS entries
        int s = __ldg(sids + tid);
        float p = (logf((float)s + 2.0f) - logf((float)s + 1.0f)) * INV_LOGV;
        g_corr[tid] = nceb[s] - logf((float)NS * p);
    }
    __syncthreads();

    // Label-row prefetch (4 rows per warp) — stacks with the gather MLP
    int    labv[4];
    float4 tb0[4], tb1[4];
    #pragma unroll
    for (int i = 0; i < 4; i++) {
        int lr = warp * 4 + i;
        labv[i] = labels[R0 + lr];
        const float* wr = ncew + (size_t)labv[i] * EMB + lane * 8;
        tb0[i] = __ldg((const float4*)wr);
        tb1[i] = __ldg((const float4*)(wr + 4));
    }

    // Embed gather: fp32 -> out (streaming), bf16 -> g_abf (L2)
    #pragma unroll
    for (int it = 0; it < K1_ROWS * (EMB / 4) / 256; it++) {   // 8 iters
        int i = it * 256 + tid;
        int r = i >> 6, c4 = i & 63;
        float4 v = __ldg((const float4*)(emb + (size_t)sRow[r] * EMB + c4 * 4));
        stcs128((float*)out + (size_t)(R0 + r) * EMB + c4 * 4, v);
        *(uint2*)(g_abf + (size_t)(R0 + r) * EMB + c4 * 4) = pack_bf16x4(v);
    }

    // True logits (embed rows L1-hot from the gather above)
    float tacc = 0.0f;
    #pragma unroll
    for (int i = 0; i < 4; i++) {
        int lr = warp * 4 + i;
        const float* er = emb + (size_t)sRow[lr] * EMB + lane * 8;
        float4 a0 = __ldg((const float4*)er);
        float4 a1 = __ldg((const float4*)(er + 4));
        float s = a0.x * tb0[i].x;
        s = fmaf(a0.y, tb0[i].y, s); s = fmaf(a0.z, tb0[i].z, s); s = fmaf(a0.w, tb0[i].w, s);
        s = fmaf(a1.x, tb1[i].x, s); s = fmaf(a1.y, tb1[i].y, s);
        s = fmaf(a1.z, tb1[i].z, s); s = fmaf(a1.w, tb1[i].w, s);
        #pragma unroll
        for (int o = 16; o; o >>= 1) s += __shfl_xor_sync(0xFFFFFFFFu, s, o);
        if (lane == 0) {
            int lab = labv[i];
            float p = (logf((float)lab + 2.0f) - logf((float)lab + 1.0f)) * INV_LOGV;
            float t = s + nceb[lab] - logf((float)NS * p);
            tacc += fmaxf(-t, 0.0f) + __logf(1.0f + __expf(-fabsf(t)));
        }
    }
    if (lane == 0) sRed[warp] = tacc;
    __syncthreads();
    if (tid == 0) {
        float v = 0.f;
        #pragma unroll
        for (int w = 0; w < 8; w++) v += sRed[w];
        g_tl[bid] = v;
    }
}

// ======================= K2: GEMM kernel =================================
// Inputs are bf16 + L2-resident; cp.async straight into smem, then MMA.
__global__ void __launch_bounds__(512, 1) w2v_gemm(float* __restrict__ out)
{
    extern __shared__ unsigned char smem_raw[];
    __nv_bfloat16* sA = (__nv_bfloat16*)smem_raw;             // [128][KPAD]
    __nv_bfloat16* sW = sA + K2_ROWS * KPAD;                  // [NS][KPAD]
    float* sCorr = (float*)(sW + (size_t)NS * KPAD);          // [NS]
    float* sRed  = (float*)(sCorr + NS);                      // [16]

    const int tid  = threadIdx.x;
    const int bid  = blockIdx.x;
    const int R0   = bid * K2_ROWS;
    const int warp = tid >> 5;
    const int lane = tid & 31;

    // cp.async: A rows (128 x 32 16B-chunks) and W rows (256 x 32) from L2
    {
        const uint32_t sAb = smem_u32(sA);
        #pragma unroll
        for (int it = 0; it < K2_ROWS * 32 / 512; it++) {     // 8 iters
            int i = it * 512 + tid;
            int r = i >> 5, c = i & 31;
            asm volatile("cp.async.cg.shared.global [%0], [%1], 16;"
                         :: "r"(sAb + r * (KPAD * 2) + c * 16),
                            "l"(g_abf + (size_t)(R0 + r) * EMB + c * 8));
        }
        const uint32_t sWb = smem_u32(sW);
        #pragma unroll
        for (int it = 0; it < NS * 32 / 512; it++) {          // 16 iters
            int i = it * 512 + tid;
            int r = i >> 5, c = i & 31;
            asm volatile("cp.async.cg.shared.global [%0], [%1], 16;"
                         :: "r"(sWb + r * (KPAD * 2) + c * 16),
                            "l"(g_wbf + (size_t)r * EMB + c * 8));
        }
        asm volatile("cp.async.commit_group;" ::: "memory");
    }
    if (tid < NS) sCorr[tid] = g_corr[tid];
    asm volatile("cp.async.wait_group 0;" ::: "memory");
    __syncthreads();

    // MMA: warp (wm 0..3, wn 0..3) owns 16 rows x 64 samples; two 64-row tiles
    const int wm = warp & 3;
    const int wn = warp >> 2;
    const int mrow  = wm * 16;
    const int nbase = wn * 64;
    const int mi = lane >> 3;
    const int arow  = mrow + (mi & 1) * 8 + (lane & 7);
    const int acolb = (mi >> 1) * 8;
    const int bRow  = nbase + (mi >> 1) * 8 + (lane & 7);
    const int bcolb = (mi & 1) * 8;
    const int q = lane & 3;

    float local = 0.0f;
    #pragma unroll
    for (int t = 0; t < 2; t++) {
        const __nv_bfloat16* sAt = sA + t * 64 * KPAD;

        float acc[8][4];
        #pragma unroll
        for (int n = 0; n < 8; n++) {
            acc[n][0] = 0.f; acc[n][1] = 0.f; acc[n][2] = 0.f; acc[n][3] = 0.f;
        }

        #pragma unroll
        for (int k = 0; k < EMB; k += 16) {
            uint32_t a0, a1, a2, a3;
            ldsm_x4(a0, a1, a2, a3, smem_u32(sAt + arow * KPAD + k + acolb));
            #pragma unroll
            for (int nn = 0; nn < 4; nn++) {
                uint32_t b0, b1, b2, b3;
                ldsm_x4(b0, b1, b2, b3, smem_u32(sW + (bRow + nn * 16) * KPAD + k + bcolb));
                mma_bf16(acc[2*nn  ][0], acc[2*nn  ][1], acc[2*nn  ][2], acc[2*nn  ][3],
                         a0, a1, a2, a3, b0, b1);
                mma_bf16(acc[2*nn+1][0], acc[2*nn+1][1], acc[2*nn+1][2], acc[2*nn+1][3],
                         a0, a1, a2, a3, b2, b3);
            }
        }

        // Epilogue: sum max(x,0) + log(prod(1+e^-|x|)) — one __logf per tile
        float prod = 1.0f;
        #pragma unroll
        for (int n = 0; n < 8; n++) {
            int c0 = nbase + n * 8 + q * 2;
            float k0 = sCorr[c0], k1 = sCorr[c0 + 1];
            #pragma unroll
            for (int j = 0; j < 4; j++) {
                float x = acc[n][j] + ((j & 1) ? k1 : k0);
                local += fmaxf(x, 0.0f);
                prod *= 1.0f + __expf(-fabsf(x));
            }
        }
        local += __logf(prod);
    }

    // ---- Deterministic block reduction -> per-block partial ----
    #pragma unroll
    for (int o = 16; o; o >>= 1) local += __shfl_xor_sync(0xFFFFFFFFu, local, o);
    if (lane == 0) sRed[warp] = local;
    __syncthreads();
    __shared__ bool sLast;
    if (tid == 0) {
        float v = 0.f;
        #pragma unroll
        for (int w = 0; w < 16; w++) v += sRed[w];
        g_partials[bid] = v;
        __threadfence();
        int old = atomicAdd(&g_count, 1);
        sLast = (old == K2_BLK - 1);
    }
    __syncthreads();

    // ---- Last block folds K2 partials + K1 true-logit partials ----
    if (sLast) {
        __threadfence();
        float v = g_tl[tid] + ((tid < K2_BLK) ? g_partials[tid] : 0.0f);
        #pragma unroll
        for (int o = 16; o; o >>= 1) v += __shfl_xor_sync(0xFFFFFFFFu, v, o);
        if (lane == 0) sRed[warp] = v;
        __syncthreads();
        if (tid == 0) {
            float t = 0.f;
            #pragma unroll
            for (int w = 0; w < 16; w++) t += sRed[w];
            out[(size_t)BATCH * EMB] = t * (1.0f / (float)BATCH);
            g_count = 0;   // reset for next graph replay
        }
    }
}

extern "C" void kernel_launch(void* const* d_in, const int* in_sizes, int n_in,
                              void* d_out, int out_size) {
    const float* emb    = (const float*)d_in[0];
    const float* ncew   = (const float*)d_in[1];
    const float* nceb   = (const float*)d_in[2];
    const int*   inputs = (const int*)d_in[3];
    const int*   labels = (const int*)d_in[4];
    const int*   sids   = (const int*)d_in[5];
    float* out = (float*)d_out;

    w2v_gather<<<K1_BLK, 256>>>(emb, ncew, nceb, inputs, labels, sids, out);

    size_t smem = (size_t)(K2_ROWS + NS) * KPAD * sizeof(__nv_bfloat16)
                + (size_t)NS * sizeof(float)
                + 16 * sizeof(float);
    cudaFuncSetAttribute(w2v_gemm, cudaFuncAttributeMaxDynamicSharedMemorySize, (int)smem);
    w2v_gemm<<<K2_BLK, 512, smem>>>(out);
}

// round 15
// speedup vs baseline: 1.0654x; 1.0654x over previous
#include <cuda_runtime.h>
#include <cuda_bf16.h>
#include <cstdint>
#include <cstddef>

#define VOCAB   100000
#define EMB     256
#define NS      256
#define BATCH   16384
#define KPAD    264              // bf16 elems per smem row (256+8 -> conflict-free ldmatrix)

#define K1_BLK  512              // gather kernel: 512 blocks x 256 thr, 32 rows each
#define K1_ROWS 32
#define K2_BLK  512              // gemm kernel: 512 blocks x 256 thr
#define K2_ROWS 64               // rows per K2 block
#define NHALF   128              // samples per K2 block

__device__ __nv_bfloat16 g_abf[BATCH * EMB];   // bf16 embed copy (8 MB, L2-resident)
__device__ __nv_bfloat16 g_wbf[NS * EMB];      // bf16 sampled weights (128 KB)
__device__ float g_corr[NS];
__device__ float g_tl[K1_BLK];                 // true-logit partials from K1
__device__ float g_partials[K2_BLK];
__device__ int   g_count = 0;

__device__ __forceinline__ uint32_t smem_u32(const void* p) {
    return (uint32_t)__cvta_generic_to_shared(p);
}

__device__ __forceinline__ void ldsm_x4(uint32_t& r0, uint32_t& r1, uint32_t& r2, uint32_t& r3,
                                        uint32_t addr) {
    asm volatile("ldmatrix.sync.aligned.m8n8.x4.shared.b16 {%0,%1,%2,%3}, [%4];"
                 : "=r"(r0), "=r"(r1), "=r"(r2), "=r"(r3) : "r"(addr));
}

__device__ __forceinline__ void mma_bf16(float& c0, float& c1, float& c2, float& c3,
                                         uint32_t a0, uint32_t a1, uint32_t a2, uint32_t a3,
                                         uint32_t b0, uint32_t b1) {
    asm volatile("mma.sync.aligned.m16n8k16.row.col.f32.bf16.bf16.f32 "
                 "{%0,%1,%2,%3}, {%4,%5,%6,%7}, {%8,%9}, {%0,%1,%2,%3};"
                 : "+f"(c0), "+f"(c1), "+f"(c2), "+f"(c3)
                 : "r"(a0), "r"(a1), "r"(a2), "r"(a3), "r"(b0), "r"(b1));
}

__device__ __forceinline__ uint2 pack_bf16x4(float4 v) {
    __nv_bfloat162 p0 = __floats2bfloat162_rn(v.x, v.y);
    __nv_bfloat162 p1 = __floats2bfloat162_rn(v.z, v.w);
    uint2 u;
    u.x = *(uint32_t*)&p0;
    u.y = *(uint32_t*)&p1;
    return u;
}

__device__ __forceinline__ void stcs128(float* p, float4 v) {
    asm volatile("st.global.cs.v4.f32 [%0], {%1,%2,%3,%4};"
                 :: "l"(p), "f"(v.x), "f"(v.y), "f"(v.z), "f"(v.w) : "memory");
}

// ======================= K1: bandwidth kernel (unchanged, at LTS cap) =====
__global__ void __launch_bounds__(256) w2v_gather(
    const float* __restrict__ emb,
    const float* __restrict__ ncew,
    const float* __restrict__ nceb,
    const int* __restrict__ inputs,
    const int* __restrict__ labels,
    const int* __restrict__ sids,
    float* __restrict__ out)
{
    __shared__ int   sRow[K1_ROWS];
    __shared__ float sRed[8];

    const int tid = threadIdx.x;
    const int bid = blockIdx.x;
    const int R0  = bid * K1_ROWS;
    const int warp = tid >> 5;
    const int lane = tid & 31;
    const float INV_LOGV = 1.0f / logf((float)VOCAB + 1.0f);

    if (tid < K1_ROWS) sRow[tid] = inputs[R0 + tid];

    if (bid < 64) {                      // W bf16 conversion: 64 blocks x 4 rows
        int r = bid * 4 + (tid >> 6), c4 = tid & 63;
        float4 v = __ldg((const float4*)(ncew + (size_t)__ldg(sids + r) * EMB + c4 * 4));
        *(uint2*)(g_wbf + (size_t)r * EMB + c4 * 4) = pack_bf16x4(v);
    } else if (bid == 64) {              // corr table
        int s = __ldg(sids + tid);
        float p = (logf((float)s + 2.0f) - logf((float)s + 1.0f)) * INV_LOGV;
        g_corr[tid] = nceb[s] - logf((float)NS * p);
    }
    __syncthreads();

    int    labv[4];
    float4 tb0[4], tb1[4];
    #pragma unroll
    for (int i = 0; i < 4; i++) {
        int lr = warp * 4 + i;
        labv[i] = labels[R0 + lr];
        const float* wr = ncew + (size_t)labv[i] * EMB + lane * 8;
        tb0[i] = __ldg((const float4*)wr);
        tb1[i] = __ldg((const float4*)(wr + 4));
    }

    #pragma unroll
    for (int it = 0; it < K1_ROWS * (EMB / 4) / 256; it++) {   // 8 iters
        int i = it * 256 + tid;
        int r = i >> 6, c4 = i & 63;
        float4 v = __ldg((const float4*)(emb + (size_t)sRow[r] * EMB + c4 * 4));
        stcs128((float*)out + (size_t)(R0 + r) * EMB + c4 * 4, v);
        *(uint2*)(g_abf + (size_t)(R0 + r) * EMB + c4 * 4) = pack_bf16x4(v);
    }

    float tacc = 0.0f;
    #pragma unroll
    for (int i = 0; i < 4; i++) {
        int lr = warp * 4 + i;
        const float* er = emb + (size_t)sRow[lr] * EMB + lane * 8;
        float4 a0 = __ldg((const float4*)er);
        float4 a1 = __ldg((const float4*)(er + 4));
        float s = a0.x * tb0[i].x;
        s = fmaf(a0.y, tb0[i].y, s); s = fmaf(a0.z, tb0[i].z, s); s = fmaf(a0.w, tb0[i].w, s);
        s = fmaf(a1.x, tb1[i].x, s); s = fmaf(a1.y, tb1[i].y, s);
        s = fmaf(a1.z, tb1[i].z, s); s = fmaf(a1.w, tb1[i].w, s);
        #pragma unroll
        for (int o = 16; o; o >>= 1) s += __shfl_xor_sync(0xFFFFFFFFu, s, o);
        if (lane == 0) {
            int lab = labv[i];
            float p = (logf((float)lab + 2.0f) - logf((float)lab + 1.0f)) * INV_LOGV;
            float t = s + nceb[lab] - logf((float)NS * p);
            tacc += fmaxf(-t, 0.0f) + __logf(1.0f + __expf(-fabsf(t)));
        }
    }
    if (lane == 0) sRed[warp] = tacc;
    __syncthreads();
    if (tid == 0) {
        float v = 0.f;
        #pragma unroll
        for (int w = 0; w < 8; w++) v += sRed[w];
        g_tl[bid] = v;
    }
}

// ======================= K2: GEMM kernel — 2 blocks/SM ====================
// 512 blocks x 256 thr: 64 rows x 128 samples each, ~101 KB smem.
__global__ void __launch_bounds__(256, 2) w2v_gemm(float* __restrict__ out)
{
    extern __shared__ unsigned char smem_raw[];
    __nv_bfloat16* sA = (__nv_bfloat16*)smem_raw;             // [64][KPAD]
    __nv_bfloat16* sW = sA + K2_ROWS * KPAD;                  // [NHALF][KPAD]
    float* sCorr = (float*)(sW + (size_t)NHALF * KPAD);       // [NHALF]
    float* sRed  = (float*)(sCorr + NHALF);                   // [8]

    const int tid  = threadIdx.x;
    const int bid  = blockIdx.x;
    const int rb   = bid >> 1;            // row block 0..255
    const int half = bid & 1;             // sample half
    const int R0   = rb * K2_ROWS;
    const int S0   = half * NHALF;
    const int warp = tid >> 5;            // 0..7
    const int lane = tid & 31;

    // cp.async from L2-resident bf16 scratch straight into smem
    {
        const uint32_t sAb = smem_u32(sA);
        #pragma unroll
        for (int it = 0; it < K2_ROWS * 32 / 256; it++) {     // 8 iters
            int i = it * 256 + tid;
            int r = i >> 5, c = i & 31;
            asm volatile("cp.async.cg.shared.global [%0], [%1], 16;"
                         :: "r"(sAb + r * (KPAD * 2) + c * 16),
                            "l"(g_abf + (size_t)(R0 + r) * EMB + c * 8));
        }
        const uint32_t sWb = smem_u32(sW);
        #pragma unroll
        for (int it = 0; it < NHALF * 32 / 256; it++) {       // 16 iters
            int i = it * 256 + tid;
            int r = i >> 5, c = i & 31;
            asm volatile("cp.async.cg.shared.global [%0], [%1], 16;"
                         :: "r"(sWb + r * (KPAD * 2) + c * 16),
                            "l"(g_wbf + (size_t)(S0 + r) * EMB + c * 8));
        }
        asm volatile("cp.async.commit_group;" ::: "memory");
    }
    if (tid < NHALF) sCorr[tid] = g_corr[S0 + tid];
    asm volatile("cp.async.wait_group 0;" ::: "memory");
    __syncthreads();

    // Warp tile 32 rows x 32 samples: 8 warps = 2 rowg x 4 colg
    const int rowg = warp & 1;
    const int colg = warp >> 1;
    const int mrow  = rowg * 32;
    const int nbase = colg * 32;
    const int mi = lane >> 3;
    const int arow  = mrow + (mi & 1) * 8 + (lane & 7);   // + mt*16
    const int acolb = (mi >> 1) * 8;
    const int bRow  = nbase + (mi >> 1) * 8 + (lane & 7); // + nt2*16
    const int bcolb = (mi & 1) * 8;
    const int q = lane & 3;

    float acc[8][4];
    #pragma unroll
    for (int n = 0; n < 8; n++) {
        acc[n][0] = 0.f; acc[n][1] = 0.f; acc[n][2] = 0.f; acc[n][3] = 0.f;
    }

    #pragma unroll
    for (int k = 0; k < EMB; k += 16) {
        uint32_t fB[8];
        #pragma unroll
        for (int nt2 = 0; nt2 < 2; nt2++)
            ldsm_x4(fB[4*nt2], fB[4*nt2+1], fB[4*nt2+2], fB[4*nt2+3],
                    smem_u32(sW + (bRow + nt2 * 16) * KPAD + k + bcolb));
        #pragma unroll
        for (int mt = 0; mt < 2; mt++) {
            uint32_t a0, a1, a2, a3;
            ldsm_x4(a0, a1, a2, a3,
                    smem_u32(sA + (arow + mt * 16) * KPAD + k + acolb));
            #pragma unroll
            for (int nt = 0; nt < 4; nt++)
                mma_bf16(acc[mt*4+nt][0], acc[mt*4+nt][1],
                         acc[mt*4+nt][2], acc[mt*4+nt][3],
                         a0, a1, a2, a3, fB[nt*2], fB[nt*2+1]);
        }
    }

    // Epilogue: sum max(x,0) + log(prod(1+e^-|x|)); 32 factors <= 2^32
    float local = 0.0f;
    float prod = 1.0f;
    #pragma unroll
    for (int mt = 0; mt < 2; mt++)
        #pragma unroll
        for (int nt = 0; nt < 4; nt++) {
            int c0 = nbase + nt * 8 + q * 2;
            float k0 = sCorr[c0], k1 = sCorr[c0 + 1];
            #pragma unroll
            for (int j = 0; j < 4; j++) {
                float x = acc[mt*4+nt][j] + ((j & 1) ? k1 : k0);
                local += fmaxf(x, 0.0f);
                prod *= 1.0f + __expf(-fabsf(x));
            }
        }
    local += __logf(prod);

    // ---- Deterministic block reduction -> per-block partial ----
    #pragma unroll
    for (int o = 16; o; o >>= 1) local += __shfl_xor_sync(0xFFFFFFFFu, local, o);
    if (lane == 0) sRed[warp] = local;
    __syncthreads();
    __shared__ bool sLast;
    if (tid == 0) {
        float v = 0.f;
        #pragma unroll
        for (int w = 0; w < 8; w++) v += sRed[w];
        g_partials[bid] = v;
        __threadfence();
        int old = atomicAdd(&g_count, 1);
        sLast = (old == K2_BLK - 1);
    }
    __syncthreads();

    // ---- Last block folds K2 partials + K1 true-logit partials ----
    if (sLast) {
        __threadfence();
        float v = g_partials[tid] + g_partials[tid + 256]
                + g_tl[tid]       + g_tl[tid + 256];
        #pragma unroll
        for (int o = 16; o; o >>= 1) v += __shfl_xor_sync(0xFFFFFFFFu, v, o);
        if (lane == 0) sRed[warp] = v;
        __syncthreads();
        if (tid == 0) {
            float t = 0.f;
            #pragma unroll
            for (int w = 0; w < 8; w++) t += sRed[w];
            out[(size_t)BATCH * EMB] = t * (1.0f / (float)BATCH);
            g_count = 0;   // reset for next graph replay
        }
    }
}

extern "C" void kernel_launch(void* const* d_in, const int* in_sizes, int n_in,
                              void* d_out, int out_size) {
    const float* emb    = (const float*)d_in[0];
    const float* ncew   = (const float*)d_in[1];
    const float* nceb   = (const float*)d_in[2];
    const int*   inputs = (const int*)d_in[3];
    const int*   labels = (const int*)d_in[4];
    const int*   sids   = (const int*)d_in[5];
    float* out = (float*)d_out;

    w2v_gather<<<K1_BLK, 256>>>(emb, ncew, nceb, inputs, labels, sids, out);

    size_t smem = (size_t)(K2_ROWS + NHALF) * KPAD * sizeof(__nv_bfloat16)
                + (size_t)NHALF * sizeof(float)
                + 8 * sizeof(float);
    cudaFuncSetAttribute(w2v_gemm, cudaFuncAttributeMaxDynamicSharedMemorySize, (int)smem);
    w2v_gemm<<<K2_BLK, 256, smem>>>(out);
}